// round 13
// baseline (speedup 1.0000x reference)
#include <cuda_runtime.h>
#include <cstdint>

// DeepSets: out[s,f] = sx_s*W[0,f] + sy_s*W[1,f] + cnt_s*b[f]
// Linearity: segment_sum(xW+b) == segment_sum(x)@W + cnt*b.
//
// KEY INSIGHT (round 12): d_out behaves like Grace host memory (~200 GB/s
// C2C: round-5 epilogue = 1MB stores = 6.08us @ DRAM 0.1%). The 1MB output
// write is a ~5.5us phase that every previous design SERIALIZED after the
// reduction. This kernel overlaps it with the stream:
//
// ONE kernel, NO grid barrier. Each warp streams its contiguous range and
// contributes per-segment partials via atomics. A 64-bit per-segment `done`
// word tracks (#contributors, first-holder warp, last-holder warp) — the
// unique last contributor finalizes the segment: writes its 64-float output
// row immediately (overlapping C2C writes with other warps' HBM streaming)
// and resets the segment's accumulators (zero-at-entry across graph replays;
// device globals start zeroed). Empty segments are zero-filled by the unique
// preceding warp. No barrier, no second phase, no separate reset pass.

#define FEAT_OUT 64
#define NSEG_MAX 4096
#define K_CTAS 608
#define K_THREADS 256
#define TOT_WARPS (K_CTAS * (K_THREADS / 32))   // 4864

__device__ float              g_px[NSEG_MAX];
__device__ float              g_py[NSEG_MAX];
__device__ int                g_cnt[NSEG_MAX];
__device__ unsigned long long g_done[NSEG_MAX];  // [0:16) cnt | [16:32) first+1 | [32:48) last+1

__device__ __forceinline__ float warp_sum(float v)
{
    #pragma unroll
    for (int o = 16; o > 0; o >>= 1) v += __shfl_xor_sync(0xFFFFFFFFu, v, o);
    return v;
}

// Warp-collective lower_bound of `target` in ids[lo,hi); all lanes return the
// same value. ~2 rounds for ranges < 1089.
__device__ __forceinline__ int warp_lower_bound(const int* __restrict__ ids,
                                                int lo, int hi, int target)
{
    const int lane = threadIdx.x & 31;
    while (hi > lo) {
        const int m = hi - lo;
        const int p = lo + (int)(((long long)m * (lane + 1)) / 33);
        const int v = __ldg(&ids[p]);
        const unsigned pred = __ballot_sync(0xFFFFFFFFu, v < target);
        const int c = __popc(pred);
        int nlo, nhi;
        if (c == 0)  nlo = lo; else nlo = lo + (int)(((long long)m * c) / 33) + 1;
        if (c == 32) nhi = hi; else nhi = lo + (int)(((long long)m * (c + 1)) / 33);
        lo = nlo; hi = nhi;
    }
    return lo;
}

// Warp-collective: add this warp's partial for segment s; if we complete the
// segment, write its output row and reset its state. Must be called from
// warp-uniform control flow.
__device__ __forceinline__ void contribute(
    int s, float sx, float sy, int scnt, bool is_first, bool is_last,
    int lane, int gw,
    const float4 w0, const float4 w1, const float4 bbv,
    float* __restrict__ out)
{
    unsigned long long post = 0ull;
    if (lane == 0) {
        atomicAdd(&g_px[s], sx);
        atomicAdd(&g_py[s], sy);
        atomicAdd(&g_cnt[s], scnt);
        __threadfence();   // publish sums before the done-add (release)
        unsigned long long delta = 1ull;
        if (is_first) delta |= ((unsigned long long)(gw + 1)) << 16;
        if (is_last)  delta |= ((unsigned long long)(gw + 1)) << 32;
        post = atomicAdd(&g_done[s], delta) + delta;
    }
    post = __shfl_sync(0xFFFFFFFFu, post, 0);
    const unsigned c = (unsigned)(post & 0xFFFFull);
    const unsigned f = (unsigned)((post >> 16) & 0xFFFFull);
    const unsigned l = (unsigned)((post >> 32) & 0xFFFFull);
    if (f != 0u && l != 0u && c == (l - f + 1u)) {
        // We are the unique final contributor: finalize segment s.
        float fx = 0.f, fy = 0.f;
        int   fc = 0;
        if (lane == 0) {
            __threadfence();   // acquire other contributors' sums
            fx = *((volatile float*)&g_px[s]);
            fy = *((volatile float*)&g_py[s]);
            fc = *((volatile int*)&g_cnt[s]);
        }
        fx = __shfl_sync(0xFFFFFFFFu, fx, 0);
        fy = __shfl_sync(0xFFFFFFFFu, fy, 0);
        fc = __shfl_sync(0xFFFFFFFFu, fc, 0);
        if (lane < 16) {
            const float cnt = (float)fc;
            float4 o;
            o.x = fmaf(fx, w0.x, fmaf(fy, w1.x, cnt * bbv.x));
            o.y = fmaf(fx, w0.y, fmaf(fy, w1.y, cnt * bbv.y));
            o.z = fmaf(fx, w0.z, fmaf(fy, w1.z, cnt * bbv.z));
            o.w = fmaf(fx, w0.w, fmaf(fy, w1.w, cnt * bbv.w));
            reinterpret_cast<float4*>(out)[s * 16 + lane] = o;
        }
        if (lane == 0) {       // sole owner now: restore zero-at-entry
            g_px[s]   = 0.f;
            g_py[s]   = 0.f;
            g_cnt[s]  = 0;
            g_done[s] = 0ull;
        }
    }
}

__device__ __forceinline__ void zero_fill(int s_from, int s_to, int lane,
                                          float* __restrict__ out)
{
    const float4 z = make_float4(0.f, 0.f, 0.f, 0.f);
    for (int s = s_from; s < s_to; s++) {
        if (lane < 16)
            reinterpret_cast<float4*>(out)[s * 16 + lane] = z;
    }
}

__global__ __launch_bounds__(K_THREADS)
void deepsets_kernel(const float4* __restrict__ xb,   // [N/2] point pairs
                     const float2* __restrict__ x2,   // [N]
                     const int*    __restrict__ ids,  // [N] sorted
                     const float*  __restrict__ W,    // [2,64]
                     const float*  __restrict__ b,    // [64]
                     float*        __restrict__ out,  // [nseg,64]
                     int N, int NF4, int num_segments)
{
    const int lane = threadIdx.x & 31;
    const int gw   = blockIdx.x * (K_THREADS / 32) + (threadIdx.x >> 5);

    // Preload epilogue operands once (lanes >=16 mirror lane&15; harmless).
    const int li = lane & 15;
    const float4 w0  = __ldg((const float4*)W + li);
    const float4 w1  = __ldg((const float4*)W + 16 + li);
    const float4 bbv = __ldg((const float4*)b + li);

    const int Q  = (NF4 + TOT_WARPS - 1) / TOT_WARPS;
    const int f0 = gw * Q;
    const int f1 = min(f0 + Q, NF4);
    if (f0 >= f1) return;

    const bool last_active = (f1 == NF4);
    const int  q0   = 2 * f0;
    const int  pend = last_active ? N : 2 * f1;   // absorb odd straggler
    const bool odd_extra = last_active && (N & 1);

    const int s_lo    = __ldg(&ids[q0]);
    const int s_hi    = __ldg(&ids[pend - 1]);
    const int prev_id = (q0 == 0) ? -1 : __ldg(&ids[q0 - 1]);
    const int next_id = (pend >= N) ? num_segments : __ldg(&ids[pend]);

    float ex = 0.f, ey = 0.f;
    if (odd_extra && lane == 0) {
        const float2 e = __ldg(&x2[N - 1]);
        ex = e.x; ey = e.y;
    }

    const int nseg = s_hi - s_lo + 1;

    if (nseg == 1) {
        float tx = 0.f, ty = 0.f;
        for (int j = f0 + lane; j < f1; j += 128) {
            const int j1 = j + 32, j2 = j + 64, j3 = j + 96;
            float4 v0 = __ldg(&xb[j]);
            float4 v1 = make_float4(0.f,0.f,0.f,0.f);
            float4 v2 = make_float4(0.f,0.f,0.f,0.f);
            float4 v3 = make_float4(0.f,0.f,0.f,0.f);
            if (j1 < f1) v1 = __ldg(&xb[j1]);
            if (j2 < f1) v2 = __ldg(&xb[j2]);
            if (j3 < f1) v3 = __ldg(&xb[j3]);
            tx += (v0.x+v0.z) + (v1.x+v1.z) + (v2.x+v2.z) + (v3.x+v3.z);
            ty += (v0.y+v0.w) + (v1.y+v1.w) + (v2.y+v2.w) + (v3.y+v3.w);
        }
        tx += ex; ty += ey;          // lane0-only extras enter the reduction
        tx = warp_sum(tx); ty = warp_sum(ty);
        contribute(s_lo, tx, ty, pend - q0,
                   prev_id < s_lo, next_id > s_hi,
                   lane, gw, w0, w1, bbv, out);
    } else if (nseg == 2) {
        const int B1 = warp_lower_bound(ids, q0 + 1, pend, s_lo + 1);
        const int jA = (B1 + 1) >> 1;   // even point 2j   >= B1
        const int jB =  B1      >> 1;   // odd  point 2j+1 >= B1
        float tx = 0.f, ty = 0.f, s1x = 0.f, s1y = 0.f;
        for (int j = f0 + lane; j < f1; j += 128) {
            const int j1 = j + 32, j2 = j + 64, j3 = j + 96;
            float4 v0 = __ldg(&xb[j]);
            float4 v1 = make_float4(0.f,0.f,0.f,0.f);
            float4 v2 = make_float4(0.f,0.f,0.f,0.f);
            float4 v3 = make_float4(0.f,0.f,0.f,0.f);
            if (j1 < f1) v1 = __ldg(&xb[j1]);
            if (j2 < f1) v2 = __ldg(&xb[j2]);
            if (j3 < f1) v3 = __ldg(&xb[j3]);
            tx += (v0.x+v0.z) + (v1.x+v1.z) + (v2.x+v2.z) + (v3.x+v3.z);
            ty += (v0.y+v0.w) + (v1.y+v1.w) + (v2.y+v2.w) + (v3.y+v3.w);
            s1x += (j  >= jA ? v0.x : 0.f) + (j  >= jB ? v0.z : 0.f)
                 + (j1 >= jA ? v1.x : 0.f) + (j1 >= jB ? v1.z : 0.f)
                 + (j2 >= jA ? v2.x : 0.f) + (j2 >= jB ? v2.z : 0.f)
                 + (j3 >= jA ? v3.x : 0.f) + (j3 >= jB ? v3.z : 0.f);
            s1y += (j  >= jA ? v0.y : 0.f) + (j  >= jB ? v0.w : 0.f)
                 + (j1 >= jA ? v1.y : 0.f) + (j1 >= jB ? v1.w : 0.f)
                 + (j2 >= jA ? v2.y : 0.f) + (j2 >= jB ? v2.w : 0.f)
                 + (j3 >= jA ? v3.y : 0.f) + (j3 >= jB ? v3.w : 0.f);
        }
        tx += ex; ty += ey; s1x += ex; s1y += ey;  // straggler is last point
        tx  = warp_sum(tx);  ty  = warp_sum(ty);
        s1x = warp_sum(s1x); s1y = warp_sum(s1y);
        contribute(s_lo, tx - s1x, ty - s1y, B1 - q0,
                   prev_id < s_lo, true,
                   lane, gw, w0, w1, bbv, out);
        contribute(s_lo + 1, s1x, s1y, pend - B1,
                   true, next_id > s_hi,
                   lane, gw, w0, w1, bbv, out);
    } else {
        // Rare generic path: walk segments sequentially (point loads cover
        // the odd straggler naturally since pend may be odd).
        int lo = q0;
        for (int s = s_lo; s <= s_hi; s++) {
            const int hi_s = (s == s_hi) ? pend
                                         : warp_lower_bound(ids, lo, pend, s + 1);
            float sx = 0.f, sy = 0.f;
            for (int i = lo + lane; i < hi_s; i += 32) {
                const float2 p = __ldg(&x2[i]);
                sx += p.x; sy += p.y;
            }
            sx = warp_sum(sx); sy = warp_sum(sy);
            contribute(s, sx, sy, hi_s - lo,
                       (s == s_lo) ? (prev_id < s_lo) : true,
                       (s == s_hi) ? (next_id > s_hi) : true,
                       lane, gw, w0, w1, bbv, out);
            lo = hi_s;
        }
    }

    // Zero-fill empty segments this warp uniquely owns.
    if (gw == 0) zero_fill(0, s_lo, lane, out);
    zero_fill(s_hi + 1, next_id, lane, out);
}

extern "C" void kernel_launch(void* const* d_in, const int* in_sizes, int n_in,
                              void* d_out, int out_size)
{
    const float* xf  = (const float*)d_in[0];    // [N,2]
    const int*   ids = (const int*)d_in[1];      // [N] sorted
    const float* W   = (const float*)d_in[2];    // [2,64]
    const float* b   = (const float*)d_in[3];    // [64]
    float* out = (float*)d_out;

    const int N   = in_sizes[0] / 2;
    const int NF4 = N / 2;
    const int num_segments = out_size / FEAT_OUT;   // 4096

    deepsets_kernel<<<K_CTAS, K_THREADS>>>(
        (const float4*)xf, (const float2*)xf, ids, W, b, out,
        N, NF4, num_segments);
}

// round 14
// speedup vs baseline: 1.1099x; 1.1099x over previous
#include <cuda_runtime.h>

// DeepSets: out[s,f] = sx_s*W[0,f] + sy_s*W[1,f] + cnt_s*b[f]
// Linearity: segment_sum(xW+b) == segment_sum(x)@W + cnt*b.
//
// K1: warp-parallel 32-ary lower_bound per segment boundary -> g_offsets.
//     (cold ~7us under ncu, ~1.5us warm in the timed graph: sampled ids
//      cache lines stay L2-resident across replays)
// K2: one CTA per segment, 4096 CTAs x 256thr, 8 resident CTAs/SM -> 3.4
//     WAVES. Early waves' 4KB/row output writes (C2C-limited ~200GB/s)
//     overlap later waves' HBM streaming — the completion staggering that
//     single-wave persistent designs cannot provide. Branch-free float2
//     loads (clamp+mask, no BSSY around loads), no atomics, no global
//     barrier, no state to reset.

#define FEAT_OUT 64
#define NSEG_MAX 4096

__device__ int g_offsets[NSEG_MAX + 1];

__device__ __forceinline__ float warp_sum(float v)
{
    #pragma unroll
    for (int o = 16; o > 0; o >>= 1) v += __shfl_xor_sync(0xFFFFFFFFu, v, o);
    return v;
}

// ---------------------------------------------------------------------------
// K1: one warp per boundary target t in [0, num_segments].
// ---------------------------------------------------------------------------
__global__ __launch_bounds__(128)
void find_offsets_kernel(const int* __restrict__ ids, int N, int num_segments)
{
    const int lane   = threadIdx.x & 31;
    const int target = blockIdx.x * 4 + (threadIdx.x >> 5);
    if (target > num_segments) return;

    int lo = 0, hi = N;
    while (hi > lo) {
        const int m = hi - lo;
        const int p = lo + (int)(((long long)m * (lane + 1)) / 33);
        const int v = __ldg(&ids[p]);
        const unsigned pred = __ballot_sync(0xFFFFFFFFu, v < target);
        const int c = __popc(pred);
        int nlo, nhi;
        if (c == 0)  nlo = lo; else nlo = lo + (int)(((long long)m * c) / 33) + 1;
        if (c == 32) nhi = hi; else nhi = lo + (int)(((long long)m * (c + 1)) / 33);
        lo = nlo; hi = nhi;
    }
    if (lane == 0) g_offsets[target] = lo;
}

// ---------------------------------------------------------------------------
// K2: one CTA per segment. Branch-free streaming, immediate output write.
// ---------------------------------------------------------------------------
__global__ __launch_bounds__(256, 8)
void segment_kernel(const float2* __restrict__ x2,   // [N] points
                    const float*  __restrict__ W,    // [2,64]
                    const float*  __restrict__ b,    // [64]
                    float*        __restrict__ out)  // [nseg,64]
{
    const int s = blockIdx.x;
    const int t = threadIdx.x;

    // Hoist writer-thread operands (L2/const-hot after wave 1).
    float4 w0, w1, bb;
    if (t < 16) {
        w0 = __ldg((const float4*)W + t);
        w1 = __ldg((const float4*)W + 16 + t);
        bb = __ldg((const float4*)b + t);
    }

    const int start = __ldg(&g_offsets[s]);
    const int end   = __ldg(&g_offsets[s + 1]);

    // Branch-free load body: 4 independent clamped+masked float2 loads.
    float sx = 0.f, sy = 0.f;
    for (int i0 = start + t; i0 < end; i0 += 1024) {
        const int i1 = i0 + 256, i2 = i0 + 512, i3 = i0 + 768;
        const float2 v0 = __ldg(&x2[i0]);                  // i0 < end in loop
        const float2 v1 = __ldg(&x2[min(i1, end - 1)]);
        const float2 v2 = __ldg(&x2[min(i2, end - 1)]);
        const float2 v3 = __ldg(&x2[min(i3, end - 1)]);
        const float m1 = (i1 < end) ? 1.f : 0.f;
        const float m2 = (i2 < end) ? 1.f : 0.f;
        const float m3 = (i3 < end) ? 1.f : 0.f;
        sx += v0.x + m1 * v1.x + m2 * v2.x + m3 * v3.x;
        sy += v0.y + m1 * v1.y + m2 * v2.y + m3 * v3.y;
    }

    sx = warp_sum(sx);
    sy = warp_sum(sy);

    __shared__ float wsx[8], wsy[8];
    const int warp = t >> 5;
    const int lane = t & 31;
    if (lane == 0) { wsx[warp] = sx; wsy[warp] = sy; }
    __syncthreads();

    if (t < 16) {
        float SX = 0.f, SY = 0.f;
        #pragma unroll
        for (int w = 0; w < 8; w++) { SX += wsx[w]; SY += wsy[w]; }
        const float cnt = (float)(end - start);
        float4 o;
        o.x = fmaf(SX, w0.x, fmaf(SY, w1.x, cnt * bb.x));
        o.y = fmaf(SX, w0.y, fmaf(SY, w1.y, cnt * bb.y));
        o.z = fmaf(SX, w0.z, fmaf(SY, w1.z, cnt * bb.z));
        o.w = fmaf(SX, w0.w, fmaf(SY, w1.w, cnt * bb.w));
        reinterpret_cast<float4*>(out)[s * 16 + t] = o;
    }
}

extern "C" void kernel_launch(void* const* d_in, const int* in_sizes, int n_in,
                              void* d_out, int out_size)
{
    const float* xf  = (const float*)d_in[0];    // [N,2]
    const int*   ids = (const int*)d_in[1];      // [N] sorted
    const float* W   = (const float*)d_in[2];    // [2,64]
    const float* b   = (const float*)d_in[3];    // [64]
    float* out = (float*)d_out;

    const int N = in_sizes[0] / 2;
    const int num_segments = out_size / FEAT_OUT;   // 4096

    const int nb1 = (num_segments + 1 + 3) / 4;
    find_offsets_kernel<<<nb1, 128>>>(ids, N, num_segments);

    segment_kernel<<<num_segments, 256>>>((const float2*)xf, W, b, out);
}

// round 15
// speedup vs baseline: 1.2623x; 1.1373x over previous
#include <cuda_runtime.h>

// DeepSets: out[s,f] = sx_s*W[0,f] + sy_s*W[1,f] + cnt_s*b[f]
// Linearity: segment_sum(xW+b) == segment_sum(x)@W + cnt*b.
//
// Round-14 diagnosis: issue=37% -> instruction-bound (overhead ~120 inst x 1M
// threads). This round: ONE WARP PER SEGMENT (4096 CTAs x 32 thr = 131K
// threads), float4 loads, no smem/syncthreads, warp-shuffle reduction only.
// ~7x fewer instructions; memory system becomes the pacer.
//
// K1: warp-parallel 32-ary lower_bound per boundary -> g_offsets (unchanged).
// K2: segment s = one warp: hoisted W/b operands, branch-free MLP-4 float4
//     interior stream + masked head/tail points, warp reduce, 16 lanes write
//     the 256B output row (C2C). Empty segments fall through to cnt=0 -> 0.

#define FEAT_OUT 64
#define NSEG_MAX 4096

__device__ int g_offsets[NSEG_MAX + 1];

__device__ __forceinline__ float warp_sum(float v)
{
    #pragma unroll
    for (int o = 16; o > 0; o >>= 1) v += __shfl_xor_sync(0xFFFFFFFFu, v, o);
    return v;
}

// ---------------------------------------------------------------------------
// K1: one warp per boundary target t in [0, num_segments].
// ---------------------------------------------------------------------------
__global__ __launch_bounds__(128)
void find_offsets_kernel(const int* __restrict__ ids, int N, int num_segments)
{
    const int lane   = threadIdx.x & 31;
    const int target = blockIdx.x * 4 + (threadIdx.x >> 5);
    if (target > num_segments) return;

    int lo = 0, hi = N;
    while (hi > lo) {
        const int m = hi - lo;
        const int p = lo + (int)(((long long)m * (lane + 1)) / 33);
        const int v = __ldg(&ids[p]);
        const unsigned pred = __ballot_sync(0xFFFFFFFFu, v < target);
        const int c = __popc(pred);
        int nlo, nhi;
        if (c == 0)  nlo = lo; else nlo = lo + (int)(((long long)m * c) / 33) + 1;
        if (c == 32) nhi = hi; else nhi = lo + (int)(((long long)m * (c + 1)) / 33);
        lo = nlo; hi = nhi;
    }
    if (lane == 0) g_offsets[target] = lo;
}

// ---------------------------------------------------------------------------
// K2: one WARP per segment. Minimal instruction count, branch-free body.
// ---------------------------------------------------------------------------
__global__ __launch_bounds__(32)
void segment_warp_kernel(const float4* __restrict__ xb,   // [N/2] point pairs
                         const float2* __restrict__ x2,   // [N] points
                         const float*  __restrict__ W,    // [2,64]
                         const float*  __restrict__ b,    // [64]
                         float*        __restrict__ out)  // [nseg,64]
{
    const int s = blockIdx.x;
    const int t = threadIdx.x;   // lane 0..31

    // Hoist epilogue operands (lanes 16..31 mirror lane&15; harmless).
    const int li = t & 15;
    const float4 w0 = __ldg((const float4*)W + li);
    const float4 w1 = __ldg((const float4*)W + 16 + li);
    const float4 bb = __ldg((const float4*)b + li);

    const int start = __ldg(&g_offsets[s]);
    const int end   = __ldg(&g_offsets[s + 1]);

    float sx = 0.f, sy = 0.f;

    // Head/tail odd points (once per CTA; lanes 0 and 1).
    if (t == 0 && (start & 1) && start < end) {
        const float2 p = __ldg(&x2[start]);
        sx += p.x; sy += p.y;
    }
    if (t == 1 && (end & 1) && end > start) {
        const float2 p = __ldg(&x2[end - 1]);
        sx += p.x; sy += p.y;
    }

    // Fully-interior float4 range: covers points [2*a0, 2*a1).
    const int a0 = (start + 1) >> 1;
    const int a1 = end >> 1;

    // Branch-free MLP-4 body (clamped addresses + arithmetic masks; loads
    // only ever execute when a1 >= 1, so a1-1 is a legal index).
    for (int j0 = a0 + t; j0 < a1; j0 += 128) {
        const int j1 = j0 + 32, j2 = j0 + 64, j3 = j0 + 96;
        const float4 v0 = __ldg(&xb[j0]);
        const float4 v1 = __ldg(&xb[min(j1, a1 - 1)]);
        const float4 v2 = __ldg(&xb[min(j2, a1 - 1)]);
        const float4 v3 = __ldg(&xb[min(j3, a1 - 1)]);
        const float m1 = (j1 < a1) ? 1.f : 0.f;
        const float m2 = (j2 < a1) ? 1.f : 0.f;
        const float m3 = (j3 < a1) ? 1.f : 0.f;
        sx += (v0.x + v0.z) + m1 * (v1.x + v1.z)
            + m2 * (v2.x + v2.z) + m3 * (v3.x + v3.z);
        sy += (v0.y + v0.w) + m1 * (v1.y + v1.w)
            + m2 * (v2.y + v2.w) + m3 * (v3.y + v3.w);
    }

    sx = warp_sum(sx);
    sy = warp_sum(sy);

    if (t < 16) {
        const float cnt = (float)(end - start);
        float4 o;
        o.x = fmaf(sx, w0.x, fmaf(sy, w1.x, cnt * bb.x));
        o.y = fmaf(sx, w0.y, fmaf(sy, w1.y, cnt * bb.y));
        o.z = fmaf(sx, w0.z, fmaf(sy, w1.z, cnt * bb.z));
        o.w = fmaf(sx, w0.w, fmaf(sy, w1.w, cnt * bb.w));
        reinterpret_cast<float4*>(out)[s * 16 + t] = o;
    }
}

extern "C" void kernel_launch(void* const* d_in, const int* in_sizes, int n_in,
                              void* d_out, int out_size)
{
    const float* xf  = (const float*)d_in[0];    // [N,2]
    const int*   ids = (const int*)d_in[1];      // [N] sorted
    const float* W   = (const float*)d_in[2];    // [2,64]
    const float* b   = (const float*)d_in[3];    // [64]
    float* out = (float*)d_out;

    const int N = in_sizes[0] / 2;
    const int num_segments = out_size / FEAT_OUT;   // 4096

    const int nb1 = (num_segments + 1 + 3) / 4;
    find_offsets_kernel<<<nb1, 128>>>(ids, N, num_segments);

    segment_warp_kernel<<<num_segments, 32>>>((const float4*)xf,
                                              (const float2*)xf, W, b, out);
}